// round 7
// baseline (speedup 1.0000x reference)
#include <cuda_runtime.h>
#include <cuda_bf16.h>
#include <cstdint>

// Problem constants
#define B_TOT 16384
#define F_TOT 32
#define D_IN  64
#define H_HID 128

#define ROWS_PER_BLK 128
#define THREADS      512
#define D2           (D_IN / 2)     // 32 k-pair steps
#define RP_STRIDE    130            // padded inner dim (rows) for rp, in 8B units
#define SMEM_ULL     (D2 * RP_STRIDE + D2 * H_HID)   // 4160 + 4096 = 8256 ULLs
#define SMEM_BYTES   (SMEM_ULL * 8)                   // 66048 bytes

// Packed fp32x2 FMA: c.lo += a.lo*b.lo ; c.hi += a.hi*b.hi (Blackwell sm_100+)
#define FMA2(c, a, b) asm("fma.rn.f32x2 %0, %1, %2, %0;" : "+l"(c) : "l"(a), "l"(b))

__global__ void __launch_bounds__(THREADS, 1)
cont_mlp_kernel(const float* __restrict__ X,
                const float* __restrict__ r_,
                const float* __restrict__ W1,
                const float* __restrict__ b1,
                const float* __restrict__ W2,
                const float* __restrict__ b2,
                float* __restrict__ out)
{
    extern __shared__ unsigned long long sm[];
    unsigned long long* rp = sm;                 // [D2][RP_STRIDE] : (r[2d2], r[2d2+1]) per row
    unsigned long long* Wp = sm + D2 * RP_STRIDE; // [D2][H]        : (W1[2d2][h], W1[2d2+1][h])

    const int f       = blockIdx.y;
    const int rowbase = blockIdx.x * ROWS_PER_BLK;
    const int t       = threadIdx.x;

    // ---- Stage W1[f] into smem, interleaving even/odd d rows into float2 pairs ----
    {
        const float* W1f = W1 + (size_t)f * D_IN * H_HID;
        float2* Wp2 = reinterpret_cast<float2*>(Wp);
        #pragma unroll
        for (int idx = t; idx < D2 * H_HID; idx += THREADS) {
            int d2 = idx >> 7;          // /128
            int h  = idx & (H_HID - 1);
            float w0 = W1f[(2 * d2)     * H_HID + h];
            float w1 = W1f[(2 * d2 + 1) * H_HID + h];
            Wp2[d2 * H_HID + h] = make_float2(w0, w1);
        }
    }

    // ---- Stage r tile: rp[d2][row] = (r[row][2d2], r[row][2d2+1]) ----
    {
        const unsigned long long* rg = reinterpret_cast<const unsigned long long*>(r_);
        #pragma unroll
        for (int idx = t; idx < ROWS_PER_BLK * D2; idx += THREADS) {
            int row = idx >> 5;          // /32
            int d2  = idx & (D2 - 1);
            // r_[(rowg*F + f)*D] as 8-byte words: 32 ULLs per (row,f)
            size_t base = ((size_t)(rowbase + row) * F_TOT + f) * D2;
            rp[d2 * RP_STRIDE + row] = rg[base + d2];
        }
    }
    __syncthreads();

    const int lane = t & 31;       // h-group: handles h = lane + 32*j
    const int w    = t >> 5;       // warp id: handles rows row0..row0+7
    const int row0 = w * 8;

    // 8 rows x 4 h-columns, each acc packed (even-d sum, odd-d sum)
    unsigned long long acc[8][4];
    #pragma unroll
    for (int m = 0; m < 8; ++m)
        #pragma unroll
        for (int j = 0; j < 4; ++j)
            acc[m][j] = 0ull;   // packed (0.0f, 0.0f)

    // ---- Main loop over 32 d-pairs ----
    #pragma unroll 4
    for (int d2 = 0; d2 < D2; ++d2) {
        // r pairs for our 8 rows (broadcast within warp; 16B-aligned vector loads)
        const ulonglong2* rrow = reinterpret_cast<const ulonglong2*>(&rp[d2 * RP_STRIDE + row0]);
        ulonglong2 ra = rrow[0];
        ulonglong2 rb = rrow[1];
        ulonglong2 rc = rrow[2];
        ulonglong2 rd = rrow[3];
        unsigned long long rr[8] = { ra.x, ra.y, rb.x, rb.y, rc.x, rc.y, rd.x, rd.y };

        // W pairs: lane-strided, conflict-free dense warp reads
        unsigned long long ww[4];
        #pragma unroll
        for (int j = 0; j < 4; ++j)
            ww[j] = Wp[d2 * H_HID + lane + 32 * j];

        #pragma unroll
        for (int m = 0; m < 8; ++m)
            #pragma unroll
            for (int j = 0; j < 4; ++j)
                FMA2(acc[m][j], rr[m], ww[j]);
    }

    // ---- Layer 2: hv = relu(lo+hi+b1); partial[m] = sum_j hv * W2 ----
    float partial[8];
    #pragma unroll
    for (int m = 0; m < 8; ++m) partial[m] = 0.0f;

    #pragma unroll
    for (int j = 0; j < 4; ++j) {
        int h = lane + 32 * j;
        float b1v = b1[f * H_HID + h];
        float w2v = W2[f * H_HID + h];
        #pragma unroll
        for (int m = 0; m < 8; ++m) {
            unsigned long long a = acc[m][j];
            float lo = __uint_as_float((unsigned)(a & 0xffffffffu));
            float hi = __uint_as_float((unsigned)(a >> 32));
            float hv = lo + hi + b1v;
            hv = fmaxf(hv, 0.0f);
            partial[m] = fmaf(hv, w2v, partial[m]);
        }
    }

    // Butterfly reduce each of the 8 row-sums across the 32 lanes
    #pragma unroll
    for (int off = 16; off > 0; off >>= 1) {
        #pragma unroll
        for (int m = 0; m < 8; ++m)
            partial[m] += __shfl_xor_sync(0xffffffffu, partial[m], off);
    }

    // Lane m (m<8) writes row row0+m
    if (lane < 8) {
        float sel = partial[0];
        #pragma unroll
        for (int m = 1; m < 8; ++m)
            sel = (lane == m) ? partial[m] : sel;

        int rowg = rowbase + row0 + lane;
        float y  = fmaxf(sel + b2[f], 0.0f);
        float xv = X[(size_t)rowg * F_TOT + f];
        reinterpret_cast<float2*>(out)[(size_t)rowg * F_TOT + f] = make_float2(xv, y);
    }
}

extern "C" void kernel_launch(void* const* d_in, const int* in_sizes, int n_in,
                              void* d_out, int out_size)
{
    const float* X  = (const float*)d_in[0];
    const float* r_ = (const float*)d_in[1];
    const float* W1 = (const float*)d_in[2];
    const float* b1 = (const float*)d_in[3];
    const float* W2 = (const float*)d_in[4];
    const float* b2 = (const float*)d_in[5];
    float* out = (float*)d_out;

    cudaFuncSetAttribute(cont_mlp_kernel,
                         cudaFuncAttributeMaxDynamicSharedMemorySize, SMEM_BYTES);

    dim3 grid(B_TOT / ROWS_PER_BLK, F_TOT);   // (128, 32)
    cont_mlp_kernel<<<grid, THREADS, SMEM_BYTES>>>(X, r_, W1, b1, W2, b2, out);
}

// round 9
// speedup vs baseline: 2.2554x; 2.2554x over previous
#include <cuda_runtime.h>
#include <cuda_bf16.h>
#include <cstdint>

// ---------------- problem constants ----------------
#define B_TOT 16384
#define F_TOT 32
#define D_IN  64
#define H_HID 128

#define THREADS      256
#define ROWS_PER_BLK 128

// smem float layout
#define A_STRIDE 68                    // 128 rows x 64 k, padded
#define B_STRIDE 136                   // 64 k x 128 h, padded
#define A_FLOATS (128 * A_STRIDE)      // 8704
#define B_FLOATS (64 * B_STRIDE)       // 8704
#define BW_OFF   (A_FLOATS + B_FLOATS) // float2 pairs (b1, w2) start here
#define SMEM_FLOATS (BW_OFF + 256)
#define SMEM_BYTES  (SMEM_FLOATS * 4)  // 70656

__device__ __forceinline__ float to_tf32(float x) {
    float y;
    asm("cvt.rna.tf32.f32 %0, %1;" : "=f"(y) : "f"(x));
    return y;
}

// m16n8k8 row.col tf32 MMA, fp32 accumulate (sm_80+ baseline PTX; HMMA on tensor pipe)
#define MMA_TF32(c, a, b)                                                 \
    asm volatile("mma.sync.aligned.m16n8k8.row.col.f32.tf32.tf32.f32 "    \
                 "{%0,%1,%2,%3}, {%4,%5,%6,%7}, {%8,%9}, {%0,%1,%2,%3};"  \
                 : "+f"((c)[0]), "+f"((c)[1]), "+f"((c)[2]), "+f"((c)[3]) \
                 : "r"((a)[0]), "r"((a)[1]), "r"((a)[2]), "r"((a)[3]),    \
                   "r"((b)[0]), "r"((b)[1]))

__global__ void __launch_bounds__(THREADS, 1)
cont_mlp_mma_kernel(const float* __restrict__ X,
                    const float* __restrict__ r_,
                    const float* __restrict__ W1,
                    const float* __restrict__ b1,
                    const float* __restrict__ W2,
                    const float* __restrict__ b2,
                    float* __restrict__ out)
{
    extern __shared__ float sm[];
    float*  A_s = sm;                                    // [128][68]
    float*  B_s = sm + A_FLOATS;                         // [64][136]
    float2* bw  = reinterpret_cast<float2*>(sm + BW_OFF); // [128] (b1, w2)

    const int f       = blockIdx.y;
    const int rowbase = blockIdx.x * ROWS_PER_BLK;
    const int t       = threadIdx.x;

    // ---- stage A = r tile [128 rows x 64 k], tf32-rounded ----
    {
        const float* rbase = r_ + ((size_t)rowbase * F_TOT + f) * D_IN;
        #pragma unroll
        for (int i = 0; i < 8; ++i) {
            int idx = t + i * THREADS;          // 0..2047 (float4 units)
            int row = idx >> 4;
            int q   = idx & 15;
            float4 v = *reinterpret_cast<const float4*>(
                rbase + (size_t)row * (F_TOT * D_IN) + q * 4);
            v.x = to_tf32(v.x); v.y = to_tf32(v.y);
            v.z = to_tf32(v.z); v.w = to_tf32(v.w);
            *reinterpret_cast<float4*>(A_s + row * A_STRIDE + q * 4) = v;
        }
    }
    // ---- stage B = W1[f] in natural [d][h] layout, tf32-rounded ----
    {
        const float* Wf = W1 + (size_t)f * D_IN * H_HID;
        #pragma unroll
        for (int i = 0; i < 8; ++i) {
            int idx = t + i * THREADS;          // 0..2047 (float4 units)
            int d = idx >> 5;
            int q = idx & 31;
            float4 v = *reinterpret_cast<const float4*>(Wf + d * H_HID + q * 4);
            v.x = to_tf32(v.x); v.y = to_tf32(v.y);
            v.z = to_tf32(v.z); v.w = to_tf32(v.w);
            *reinterpret_cast<float4*>(B_s + d * B_STRIDE + q * 4) = v;
        }
    }
    if (t < H_HID)
        bw[t] = make_float2(b1[f * H_HID + t], W2[f * H_HID + t]);
    __syncthreads();

    const int wid  = t >> 5;
    const int lane = t & 31;
    const int mgrp = wid >> 2;      // 0..1 : rows [mgrp*64, +64)
    const int ngrp = wid & 3;       // 0..3 : cols [ngrp*32, +32)
    const int qrow = lane >> 2;     // 0..7
    const int qcol = lane & 3;      // 0..3

    float acc[4][4][4];             // [m-tile][n-tile][frag reg]
    #pragma unroll
    for (int mt = 0; mt < 4; ++mt)
        #pragma unroll
        for (int nt = 0; nt < 4; ++nt)
            #pragma unroll
            for (int rr = 0; rr < 4; ++rr)
                acc[mt][nt][rr] = 0.0f;

    // ---- k-loop: 8 steps of k=8 ----
    #pragma unroll
    for (int ks = 0; ks < 8; ++ks) {
        uint32_t a[4][4];
        #pragma unroll
        for (int mt = 0; mt < 4; ++mt) {
            const float* ap = A_s + (mgrp * 64 + mt * 16 + qrow) * A_STRIDE
                                  + ks * 8 + qcol;
            a[mt][0] = __float_as_uint(ap[0]);
            a[mt][1] = __float_as_uint(ap[8 * A_STRIDE]);
            a[mt][2] = __float_as_uint(ap[4]);
            a[mt][3] = __float_as_uint(ap[8 * A_STRIDE + 4]);
        }
        uint32_t b[4][2];
        #pragma unroll
        for (int nt = 0; nt < 4; ++nt) {
            const float* bp = B_s + (ks * 8 + qcol) * B_STRIDE
                                  + ngrp * 32 + nt * 8 + qrow;
            b[nt][0] = __float_as_uint(bp[0]);
            b[nt][1] = __float_as_uint(bp[4 * B_STRIDE]);
        }
        #pragma unroll
        for (int mt = 0; mt < 4; ++mt)
            #pragma unroll
            for (int nt = 0; nt < 4; ++nt)
                MMA_TF32(acc[mt][nt], a[mt], b[nt]);
    }

    // ---- epilogue: relu(+b1)*w2, sum over this warp's 32 cols ----
    // frag: reg0=(qrow, 2qcol) reg1=(qrow, 2qcol+1) reg2/3 = +8 rows
    float part[4][2];               // [m-tile][row-half]
    #pragma unroll
    for (int mt = 0; mt < 4; ++mt) {
        #pragma unroll
        for (int hf = 0; hf < 2; ++hf) {
            float s = 0.0f;
            #pragma unroll
            for (int nt = 0; nt < 4; ++nt) {
                int col = ngrp * 32 + nt * 8 + qcol * 2;
                float2 p0 = bw[col];
                float2 p1 = bw[col + 1];
                float d0 = fmaxf(acc[mt][nt][hf * 2 + 0] + p0.x, 0.0f);
                float d1 = fmaxf(acc[mt][nt][hf * 2 + 1] + p1.x, 0.0f);
                s = fmaf(d0, p0.y, s);
                s = fmaf(d1, p1.y, s);
            }
            part[mt][hf] = s;
        }
    }
    // quad reduce across qcol (lanes qrow*4 + {0..3})
    #pragma unroll
    for (int off = 1; off < 4; off <<= 1)
        #pragma unroll
        for (int mt = 0; mt < 4; ++mt)
            #pragma unroll
            for (int hf = 0; hf < 2; ++hf)
                part[mt][hf] += __shfl_xor_sync(0xffffffffu, part[mt][hf], off);

    // ---- cross-warp (4 ngrp) reduction via smem buffer (reuse A_s) ----
    __syncthreads();                // all warps done reading A_s/B_s
    float* buf = A_s;               // [128][5] padded
    if (qcol == 0) {
        #pragma unroll
        for (int mt = 0; mt < 4; ++mt)
            #pragma unroll
            for (int hf = 0; hf < 2; ++hf) {
                int row = mgrp * 64 + mt * 16 + hf * 8 + qrow;
                buf[row * 5 + ngrp] = part[mt][hf];
            }
    }
    __syncthreads();

    if (t < ROWS_PER_BLK) {
        float s = buf[t * 5 + 0] + buf[t * 5 + 1]
                + buf[t * 5 + 2] + buf[t * 5 + 3];
        float y  = fmaxf(s + b2[f], 0.0f);
        int rowg = rowbase + t;
        float xv = X[(size_t)rowg * F_TOT + f];
        reinterpret_cast<float2*>(out)[(size_t)rowg * F_TOT + f] = make_float2(xv, y);
    }
}

// ---------------- launch ----------------
extern "C" void kernel_launch(void* const* d_in, const int* in_sizes, int n_in,
                              void* d_out, int out_size)
{
    const float* X  = (const float*)d_in[0];
    const float* r_ = (const float*)d_in[1];
    const float* W1 = (const float*)d_in[2];
    const float* b1 = (const float*)d_in[3];
    const float* W2 = (const float*)d_in[4];
    const float* b2 = (const float*)d_in[5];
    float* out = (float*)d_out;

    cudaFuncSetAttribute(cont_mlp_mma_kernel,
                         cudaFuncAttributeMaxDynamicSharedMemorySize, SMEM_BYTES);

    dim3 grid(B_TOT / ROWS_PER_BLK, F_TOT);   // (128, 32)
    cont_mlp_mma_kernel<<<grid, THREADS, SMEM_BYTES>>>(X, r_, W1, b1, W2, b2, out);
}

// round 10
// speedup vs baseline: 2.2625x; 1.0032x over previous
#include <cuda_runtime.h>
#include <cuda_bf16.h>
#include <cstdint>

// ---------------- problem constants ----------------
#define B_TOT 16384
#define F_TOT 32
#define D_IN  64
#define H_HID 128

#define THREADS      256
#define ROWS_PER_BLK 128

// smem float layout
#define A_STRIDE 68                    // 128 rows x 64 k, padded
#define B_STRIDE 136                   // 64 k x 128 h, padded
#define A_FLOATS (128 * A_STRIDE)      // 8704
#define B_FLOATS (64 * B_STRIDE)       // 8704
#define BW_OFF   (A_FLOATS + B_FLOATS) // float2 pairs (b1, w2) start here
#define SMEM_FLOATS (BW_OFF + 256)
#define SMEM_BYTES  (SMEM_FLOATS * 4)  // 70656

__device__ __forceinline__ float to_tf32(float x) {
    float y;
    asm("cvt.rna.tf32.f32 %0, %1;" : "=f"(y) : "f"(x));
    return y;
}

// m16n8k8 row.col tf32 MMA, fp32 accumulate (sm_80+ baseline PTX; HMMA on tensor pipe)
#define MMA_TF32(c, a, b)                                                 \
    asm volatile("mma.sync.aligned.m16n8k8.row.col.f32.tf32.tf32.f32 "    \
                 "{%0,%1,%2,%3}, {%4,%5,%6,%7}, {%8,%9}, {%0,%1,%2,%3};"  \
                 : "+f"((c)[0]), "+f"((c)[1]), "+f"((c)[2]), "+f"((c)[3]) \
                 : "r"((a)[0]), "r"((a)[1]), "r"((a)[2]), "r"((a)[3]),    \
                   "r"((b)[0]), "r"((b)[1]))

__global__ void __launch_bounds__(THREADS, 1)
cont_mlp_mma_kernel(const float* __restrict__ X,
                    const float* __restrict__ r_,
                    const float* __restrict__ W1,
                    const float* __restrict__ b1,
                    const float* __restrict__ W2,
                    const float* __restrict__ b2,
                    float* __restrict__ out)
{
    extern __shared__ float sm[];
    float*  A_s = sm;                                    // [128][68]
    float*  B_s = sm + A_FLOATS;                         // [64][136]
    float2* bw  = reinterpret_cast<float2*>(sm + BW_OFF); // [128] (b1, w2)

    const int f       = blockIdx.y;
    const int rowbase = blockIdx.x * ROWS_PER_BLK;
    const int t       = threadIdx.x;

    // ---- stage A = r tile [128 rows x 64 k], tf32-rounded ----
    {
        const float* rbase = r_ + ((size_t)rowbase * F_TOT + f) * D_IN;
        #pragma unroll
        for (int i = 0; i < 8; ++i) {
            int idx = t + i * THREADS;          // 0..2047 (float4 units)
            int row = idx >> 4;
            int q   = idx & 15;
            float4 v = *reinterpret_cast<const float4*>(
                rbase + (size_t)row * (F_TOT * D_IN) + q * 4);
            v.x = to_tf32(v.x); v.y = to_tf32(v.y);
            v.z = to_tf32(v.z); v.w = to_tf32(v.w);
            *reinterpret_cast<float4*>(A_s + row * A_STRIDE + q * 4) = v;
        }
    }
    // ---- stage B = W1[f] in natural [d][h] layout, tf32-rounded ----
    {
        const float* Wf = W1 + (size_t)f * D_IN * H_HID;
        #pragma unroll
        for (int i = 0; i < 8; ++i) {
            int idx = t + i * THREADS;          // 0..2047 (float4 units)
            int d = idx >> 5;
            int q = idx & 31;
            float4 v = *reinterpret_cast<const float4*>(Wf + d * H_HID + q * 4);
            v.x = to_tf32(v.x); v.y = to_tf32(v.y);
            v.z = to_tf32(v.z); v.w = to_tf32(v.w);
            *reinterpret_cast<float4*>(B_s + d * B_STRIDE + q * 4) = v;
        }
    }
    if (t < H_HID)
        bw[t] = make_float2(b1[f * H_HID + t], W2[f * H_HID + t]);
    __syncthreads();

    const int wid  = t >> 5;
    const int lane = t & 31;
    const int mgrp = wid >> 2;      // 0..1 : rows [mgrp*64, +64)
    const int ngrp = wid & 3;       // 0..3 : cols [ngrp*32, +32)
    const int qrow = lane >> 2;     // 0..7
    const int qcol = lane & 3;      // 0..3

    float acc[4][4][4];             // [m-tile][n-tile][frag reg]
    #pragma unroll
    for (int mt = 0; mt < 4; ++mt)
        #pragma unroll
        for (int nt = 0; nt < 4; ++nt)
            #pragma unroll
            for (int rr = 0; rr < 4; ++rr)
                acc[mt][nt][rr] = 0.0f;

    // ---- k-loop: 8 steps of k=8 ----
    #pragma unroll
    for (int ks = 0; ks < 8; ++ks) {
        uint32_t a[4][4];
        #pragma unroll
        for (int mt = 0; mt < 4; ++mt) {
            const float* ap = A_s + (mgrp * 64 + mt * 16 + qrow) * A_STRIDE
                                  + ks * 8 + qcol;
            a[mt][0] = __float_as_uint(ap[0]);
            a[mt][1] = __float_as_uint(ap[8 * A_STRIDE]);
            a[mt][2] = __float_as_uint(ap[4]);
            a[mt][3] = __float_as_uint(ap[8 * A_STRIDE + 4]);
        }
        uint32_t b[4][2];
        #pragma unroll
        for (int nt = 0; nt < 4; ++nt) {
            const float* bp = B_s + (ks * 8 + qcol) * B_STRIDE
                                  + ngrp * 32 + nt * 8 + qrow;
            b[nt][0] = __float_as_uint(bp[0]);
            b[nt][1] = __float_as_uint(bp[4 * B_STRIDE]);
        }
        #pragma unroll
        for (int mt = 0; mt < 4; ++mt)
            #pragma unroll
            for (int nt = 0; nt < 4; ++nt)
                MMA_TF32(acc[mt][nt], a[mt], b[nt]);
    }

    // ---- epilogue: relu(+b1)*w2, sum over this warp's 32 cols ----
    // frag: reg0=(qrow, 2qcol) reg1=(qrow, 2qcol+1) reg2/3 = +8 rows
    float part[4][2];               // [m-tile][row-half]
    #pragma unroll
    for (int mt = 0; mt < 4; ++mt) {
        #pragma unroll
        for (int hf = 0; hf < 2; ++hf) {
            float s = 0.0f;
            #pragma unroll
            for (int nt = 0; nt < 4; ++nt) {
                int col = ngrp * 32 + nt * 8 + qcol * 2;
                float2 p0 = bw[col];
                float2 p1 = bw[col + 1];
                float d0 = fmaxf(acc[mt][nt][hf * 2 + 0] + p0.x, 0.0f);
                float d1 = fmaxf(acc[mt][nt][hf * 2 + 1] + p1.x, 0.0f);
                s = fmaf(d0, p0.y, s);
                s = fmaf(d1, p1.y, s);
            }
            part[mt][hf] = s;
        }
    }
    // quad reduce across qcol (lanes qrow*4 + {0..3})
    #pragma unroll
    for (int off = 1; off < 4; off <<= 1)
        #pragma unroll
        for (int mt = 0; mt < 4; ++mt)
            #pragma unroll
            for (int hf = 0; hf < 2; ++hf)
                part[mt][hf] += __shfl_xor_sync(0xffffffffu, part[mt][hf], off);

    // ---- cross-warp (4 ngrp) reduction via smem buffer (reuse A_s) ----
    __syncthreads();                // all warps done reading A_s/B_s
    float* buf = A_s;               // [128][5] padded
    if (qcol == 0) {
        #pragma unroll
        for (int mt = 0; mt < 4; ++mt)
            #pragma unroll
            for (int hf = 0; hf < 2; ++hf) {
                int row = mgrp * 64 + mt * 16 + hf * 8 + qrow;
                buf[row * 5 + ngrp] = part[mt][hf];
            }
    }
    __syncthreads();

    if (t < ROWS_PER_BLK) {
        float s = buf[t * 5 + 0] + buf[t * 5 + 1]
                + buf[t * 5 + 2] + buf[t * 5 + 3];
        float y  = fmaxf(s + b2[f], 0.0f);
        int rowg = rowbase + t;
        float xv = X[(size_t)rowg * F_TOT + f];
        reinterpret_cast<float2*>(out)[(size_t)rowg * F_TOT + f] = make_float2(xv, y);
    }
}

// ---------------- launch ----------------
extern "C" void kernel_launch(void* const* d_in, const int* in_sizes, int n_in,
                              void* d_out, int out_size)
{
    const float* X  = (const float*)d_in[0];
    const float* r_ = (const float*)d_in[1];
    const float* W1 = (const float*)d_in[2];
    const float* b1 = (const float*)d_in[3];
    const float* W2 = (const float*)d_in[4];
    const float* b2 = (const float*)d_in[5];
    float* out = (float*)d_out;

    cudaFuncSetAttribute(cont_mlp_mma_kernel,
                         cudaFuncAttributeMaxDynamicSharedMemorySize, SMEM_BYTES);

    dim3 grid(B_TOT / ROWS_PER_BLK, F_TOT);   // (128, 32)
    cont_mlp_mma_kernel<<<grid, THREADS, SMEM_BYTES>>>(X, r_, W1, b1, W2, b2, out);
}

// round 11
// speedup vs baseline: 2.9161x; 1.2889x over previous
#include <cuda_runtime.h>
#include <cuda_bf16.h>
#include <cstdint>

// ---------------- problem constants ----------------
#define B_TOT 16384
#define F_TOT 32
#define D_IN  64
#define H_HID 128

#define THREADS       256
#define TILES         4
#define ROWS_PER_TILE 128
#define ROWS_PER_BLK  (TILES * ROWS_PER_TILE)   // 512

// smem float layout
#define A_STRIDE 68                     // 128 rows x 64 k, padded
#define B_STRIDE 136                    // 64 k x 128 h, padded
#define A_FLOATS (128 * A_STRIDE)       // 8704
#define B_FLOATS (64 * B_STRIDE)        // 8704
#define BW_OFF   (A_FLOATS + B_FLOATS)  // float2 pairs (b1, w2)
#define EP_OFF   (BW_OFF + 256)         // epilogue buffer [128][5]
#define SMEM_FLOATS (EP_OFF + 640)
#define SMEM_BYTES  (SMEM_FLOATS * 4)   // 73216 -> 2 CTAs/SM = 146KB < 228KB

__device__ __forceinline__ float to_tf32(float x) {
    float y;
    asm("cvt.rna.tf32.f32 %0, %1;" : "=f"(y) : "f"(x));
    return y;
}

// m16n8k8 row.col tf32 MMA, fp32 accumulate (sm_80+ baseline PTX)
#define MMA_TF32(c, a, b)                                                 \
    asm volatile("mma.sync.aligned.m16n8k8.row.col.f32.tf32.tf32.f32 "    \
                 "{%0,%1,%2,%3}, {%4,%5,%6,%7}, {%8,%9}, {%0,%1,%2,%3};"  \
                 : "+f"((c)[0]), "+f"((c)[1]), "+f"((c)[2]), "+f"((c)[3]) \
                 : "r"((a)[0]), "r"((a)[1]), "r"((a)[2]), "r"((a)[3]),    \
                   "r"((b)[0]), "r"((b)[1]))

__global__ void __launch_bounds__(THREADS, 2)
cont_mlp_mma_kernel(const float* __restrict__ X,
                    const float* __restrict__ r_,
                    const float* __restrict__ W1,
                    const float* __restrict__ b1,
                    const float* __restrict__ W2,
                    const float* __restrict__ b2,
                    float* __restrict__ out)
{
    extern __shared__ float sm[];
    float*  A_s = sm;                                     // [128][68]
    float*  B_s = sm + A_FLOATS;                          // [64][136]
    float2* bw  = reinterpret_cast<float2*>(sm + BW_OFF); // [128] (b1, w2)
    float*  ep  = sm + EP_OFF;                            // [128][5]

    const int f        = blockIdx.y;
    const int rowbase0 = blockIdx.x * ROWS_PER_BLK;
    const int t        = threadIdx.x;

    const int wid  = t >> 5;
    const int lane = t & 31;
    const int mgrp = wid >> 2;      // 0..1 : rows [mgrp*64, +64)
    const int ngrp = wid & 3;       // 0..3 : cols [ngrp*32, +32)
    const int qrow = lane >> 2;     // 0..7
    const int qcol = lane & 3;      // 0..3

    // ---- stage B = W1[f] (natural [d][h]) once per block, tf32-rounded ----
    {
        const float* Wf = W1 + (size_t)f * D_IN * H_HID;
        #pragma unroll
        for (int i = 0; i < 8; ++i) {
            int idx = t + i * THREADS;      // 0..2047 float4 units
            int d = idx >> 5;
            int q = idx & 31;
            float4 v = *reinterpret_cast<const float4*>(Wf + d * H_HID + q * 4);
            v.x = to_tf32(v.x); v.y = to_tf32(v.y);
            v.z = to_tf32(v.z); v.w = to_tf32(v.w);
            *reinterpret_cast<float4*>(B_s + d * B_STRIDE + q * 4) = v;
        }
    }
    if (t < H_HID)
        bw[t] = make_float2(b1[f * H_HID + t], W2[f * H_HID + t]);
    const float b2v = b2[f];

    #pragma unroll 1
    for (int tile = 0; tile < TILES; ++tile) {
        const int rowbase = rowbase0 + tile * ROWS_PER_TILE;

        // ---- stage A = r tile [128 rows x 64 k], tf32-rounded ----
        {
            const float* rbase = r_ + ((size_t)rowbase * F_TOT + f) * D_IN;
            #pragma unroll
            for (int i = 0; i < 8; ++i) {
                int idx = t + i * THREADS;  // 0..2047 float4 units
                int row = idx >> 4;
                int q   = idx & 15;
                float4 v = *reinterpret_cast<const float4*>(
                    rbase + (size_t)row * (F_TOT * D_IN) + q * 4);
                v.x = to_tf32(v.x); v.y = to_tf32(v.y);
                v.z = to_tf32(v.z); v.w = to_tf32(v.w);
                *reinterpret_cast<float4*>(A_s + row * A_STRIDE + q * 4) = v;
            }
        }
        __syncthreads();    // A_s (+ B_s/bw on tile 0) visible; prev-tile ep reads done

        float acc[4][4][4];
        #pragma unroll
        for (int mt = 0; mt < 4; ++mt)
            #pragma unroll
            for (int nt = 0; nt < 4; ++nt)
                #pragma unroll
                for (int rr = 0; rr < 4; ++rr)
                    acc[mt][nt][rr] = 0.0f;

        // ---- k-loop: 8 steps of k=8 ----
        #pragma unroll
        for (int ks = 0; ks < 8; ++ks) {
            uint32_t a[4][4];
            #pragma unroll
            for (int mt = 0; mt < 4; ++mt) {
                const float* ap = A_s + (mgrp * 64 + mt * 16 + qrow) * A_STRIDE
                                      + ks * 8 + qcol;
                a[mt][0] = __float_as_uint(ap[0]);
                a[mt][1] = __float_as_uint(ap[8 * A_STRIDE]);
                a[mt][2] = __float_as_uint(ap[4]);
                a[mt][3] = __float_as_uint(ap[8 * A_STRIDE + 4]);
            }
            uint32_t b[4][2];
            #pragma unroll
            for (int nt = 0; nt < 4; ++nt) {
                const float* bp = B_s + (ks * 8 + qcol) * B_STRIDE
                                      + ngrp * 32 + nt * 8 + qrow;
                b[nt][0] = __float_as_uint(bp[0]);
                b[nt][1] = __float_as_uint(bp[4 * B_STRIDE]);
            }
            #pragma unroll
            for (int mt = 0; mt < 4; ++mt)
                #pragma unroll
                for (int nt = 0; nt < 4; ++nt)
                    MMA_TF32(acc[mt][nt], a[mt], b[nt]);
        }

        // ---- epilogue: relu(+b1)*w2, sum over this warp's 32 cols ----
        // frag: reg0=(qrow, 2qcol) reg1=(qrow, 2qcol+1), reg2/3 = +8 rows
        float part[4][2];
        #pragma unroll
        for (int mt = 0; mt < 4; ++mt) {
            #pragma unroll
            for (int hf = 0; hf < 2; ++hf) {
                float s = 0.0f;
                #pragma unroll
                for (int nt = 0; nt < 4; ++nt) {
                    int col = ngrp * 32 + nt * 8 + qcol * 2;
                    float2 p0 = bw[col];
                    float2 p1 = bw[col + 1];
                    float d0 = fmaxf(acc[mt][nt][hf * 2 + 0] + p0.x, 0.0f);
                    float d1 = fmaxf(acc[mt][nt][hf * 2 + 1] + p1.x, 0.0f);
                    s = fmaf(d0, p0.y, s);
                    s = fmaf(d1, p1.y, s);
                }
                part[mt][hf] = s;
            }
        }
        // quad reduce across qcol (lanes qrow*4 + {0..3})
        #pragma unroll
        for (int off = 1; off < 4; off <<= 1)
            #pragma unroll
            for (int mt = 0; mt < 4; ++mt)
                #pragma unroll
                for (int hf = 0; hf < 2; ++hf)
                    part[mt][hf] += __shfl_xor_sync(0xffffffffu, part[mt][hf], off);

        // ---- cross-warp (4 ngrp) reduction via dedicated smem buffer ----
        if (qcol == 0) {
            #pragma unroll
            for (int mt = 0; mt < 4; ++mt)
                #pragma unroll
                for (int hf = 0; hf < 2; ++hf) {
                    int row = mgrp * 64 + mt * 16 + hf * 8 + qrow;
                    ep[row * 5 + ngrp] = part[mt][hf];
                }
        }
        __syncthreads();    // also guarantees all k-loop A_s reads are done

        if (t < ROWS_PER_TILE) {
            float s = ep[t * 5 + 0] + ep[t * 5 + 1]
                    + ep[t * 5 + 2] + ep[t * 5 + 3];
            float y  = fmaxf(s + b2v, 0.0f);
            int rowg = rowbase + t;
            float xv = X[(size_t)rowg * F_TOT + f];
            reinterpret_cast<float2*>(out)[(size_t)rowg * F_TOT + f] =
                make_float2(xv, y);
        }
        // next tile's A staging may start; its pre-kloop barrier orders ep reads
    }
}

// ---------------- launch ----------------
extern "C" void kernel_launch(void* const* d_in, const int* in_sizes, int n_in,
                              void* d_out, int out_size)
{
    const float* X  = (const float*)d_in[0];
    const float* r_ = (const float*)d_in[1];
    const float* W1 = (const float*)d_in[2];
    const float* b1 = (const float*)d_in[3];
    const float* W2 = (const float*)d_in[4];
    const float* b2 = (const float*)d_in[5];
    float* out = (float*)d_out;

    cudaFuncSetAttribute(cont_mlp_mma_kernel,
                         cudaFuncAttributeMaxDynamicSharedMemorySize, SMEM_BYTES);

    dim3 grid(B_TOT / ROWS_PER_BLK, F_TOT);   // (32, 32)
    cont_mlp_mma_kernel<<<grid, THREADS, SMEM_BYTES>>>(X, r_, W1, b1, W2, b2, out);
}

// round 12
// speedup vs baseline: 3.4447x; 1.1812x over previous
#include <cuda_runtime.h>
#include <cuda_bf16.h>
#include <cstdint>

// ---------------- problem constants ----------------
#define B_TOT 16384
#define F_TOT 32
#define D_IN  64
#define H_HID 128

#define THREADS       256
#define TILES         4
#define ROWS_PER_TILE 128
#define ROWS_PER_BLK  (TILES * ROWS_PER_TILE)   // 512

// smem float layout: A double-buffered
#define A_STRIDE 68                       // 128 rows x 64 k, padded (rows 16B-aligned)
#define B_STRIDE 136                      // 64 k x 128 h, padded
#define A_FLOATS (128 * A_STRIDE)         // 8704
#define B_FLOATS (64 * B_STRIDE)          // 8704
#define B_OFF    (2 * A_FLOATS)           // after the two A buffers
#define BW_OFF   (B_OFF + B_FLOATS)       // float2 pairs (b1, w2)
#define EP_OFF   (BW_OFF + 256)           // epilogue buffer [128][5]
#define SMEM_FLOATS (EP_OFF + 640)
#define SMEM_BYTES  (SMEM_FLOATS * 4)     // 108,032 B -> 2 CTAs = 216KB < 228KB

__device__ __forceinline__ float to_tf32(float x) {
    float y;
    asm("cvt.rna.tf32.f32 %0, %1;" : "=f"(y) : "f"(x));
    return y;
}
__device__ __forceinline__ uint32_t smem_u32(const void* p) {
    uint32_t a;
    asm("{ .reg .u64 t; cvta.to.shared.u64 t, %1; cvt.u32.u64 %0, t; }" : "=r"(a) : "l"(p));
    return a;
}

#define CP_ASYNC16(dst_u32, src_ptr) \
    asm volatile("cp.async.cg.shared.global [%0], [%1], 16;" \
                 :: "r"(dst_u32), "l"(src_ptr) : "memory")
#define CP_ASYNC_COMMIT() asm volatile("cp.async.commit_group;" ::: "memory")
#define CP_ASYNC_WAIT(n)  asm volatile("cp.async.wait_group %0;" :: "n"(n) : "memory")

// m16n8k8 row.col tf32 MMA, fp32 accumulate (sm_80+ baseline PTX)
#define MMA_TF32(c, a, b)                                                 \
    asm volatile("mma.sync.aligned.m16n8k8.row.col.f32.tf32.tf32.f32 "    \
                 "{%0,%1,%2,%3}, {%4,%5,%6,%7}, {%8,%9}, {%0,%1,%2,%3};"  \
                 : "+f"((c)[0]), "+f"((c)[1]), "+f"((c)[2]), "+f"((c)[3]) \
                 : "r"((a)[0]), "r"((a)[1]), "r"((a)[2]), "r"((a)[3]),    \
                   "r"((b)[0]), "r"((b)[1]))

__global__ void __launch_bounds__(THREADS, 2)
cont_mlp_mma_kernel(const float* __restrict__ X,
                    const float* __restrict__ r_,
                    const float* __restrict__ W1,
                    const float* __restrict__ b1,
                    const float* __restrict__ W2,
                    const float* __restrict__ b2,
                    float* __restrict__ out)
{
    extern __shared__ float sm[];
    float*  B_s = sm + B_OFF;                             // [64][136]
    float2* bw  = reinterpret_cast<float2*>(sm + BW_OFF); // [128] (b1, w2)
    float*  ep  = sm + EP_OFF;                            // [128][5]
    const uint32_t smb = smem_u32(sm);

    const int f        = blockIdx.y;
    const int rowbase0 = blockIdx.x * ROWS_PER_BLK;
    const int t        = threadIdx.x;

    const int wid  = t >> 5;
    const int lane = t & 31;
    const int mgrp = wid >> 2;      // 0..1 : rows [mgrp*64, +64)
    const int ngrp = wid & 3;       // 0..3 : cols [ngrp*32, +32)
    const int qrow = lane >> 2;     // 0..7
    const int qcol = lane & 3;      // 0..3

    // per-thread A-staging indices (8 float4 chunks per tile)
    const int arow = t >> 1;                 // two threads per row... see below
    // (we use idx = t + i*THREADS; row = idx>>4, q = idx&15)

    const float* rfeat = r_ + (size_t)f * D_IN;   // row stride = F_TOT*D_IN floats

    // ---- issue cp.async for tile 0 into buffer 0 ----
    {
        const float* rbase = rfeat + (size_t)rowbase0 * (F_TOT * D_IN);
        #pragma unroll
        for (int i = 0; i < 8; ++i) {
            int idx = t + i * THREADS;      // 0..2047 float4 units
            int row = idx >> 4;
            int q   = idx & 15;
            uint32_t dst = smb + (uint32_t)((row * A_STRIDE + q * 4) * 4);
            CP_ASYNC16(dst, rbase + (size_t)row * (F_TOT * D_IN) + q * 4);
        }
        CP_ASYNC_COMMIT();
    }

    // ---- stage B = W1[f] (natural [d][h]) once per block, tf32-rounded ----
    {
        const float* Wf = W1 + (size_t)f * D_IN * H_HID;
        #pragma unroll
        for (int i = 0; i < 8; ++i) {
            int idx = t + i * THREADS;      // 0..2047 float4 units
            int d = idx >> 5;
            int q = idx & 31;
            float4 v = *reinterpret_cast<const float4*>(Wf + d * H_HID + q * 4);
            v.x = to_tf32(v.x); v.y = to_tf32(v.y);
            v.z = to_tf32(v.z); v.w = to_tf32(v.w);
            *reinterpret_cast<float4*>(B_s + d * B_STRIDE + q * 4) = v;
        }
    }
    if (t < H_HID)
        bw[t] = make_float2(b1[f * H_HID + t], W2[f * H_HID + t]);
    const float b2v = b2[f];

    #pragma unroll 1
    for (int tile = 0; tile < TILES; ++tile) {
        const int rowbase = rowbase0 + tile * ROWS_PER_TILE;
        float* A_s = sm + (tile & 1) * A_FLOATS;

        // ---- issue cp.async for tile+1 into the other buffer ----
        if (tile + 1 < TILES) {
            const float* rbase = rfeat +
                (size_t)(rowbase0 + (tile + 1) * ROWS_PER_TILE) * (F_TOT * D_IN);
            uint32_t abuf = smb + (uint32_t)(((tile + 1) & 1) * A_FLOATS * 4);
            #pragma unroll
            for (int i = 0; i < 8; ++i) {
                int idx = t + i * THREADS;
                int row = idx >> 4;
                int q   = idx & 15;
                uint32_t dst = abuf + (uint32_t)((row * A_STRIDE + q * 4) * 4);
                CP_ASYNC16(dst, rbase + (size_t)row * (F_TOT * D_IN) + q * 4);
            }
            CP_ASYNC_COMMIT();
            CP_ASYNC_WAIT(1);     // current tile's group is complete
        } else {
            CP_ASYNC_WAIT(0);
        }
        __syncthreads();          // A_s visible (+ B_s/bw on tile 0; ep reads of t-1 done)

        float acc[4][4][4];
        #pragma unroll
        for (int mt = 0; mt < 4; ++mt)
            #pragma unroll
            for (int nt = 0; nt < 4; ++nt)
                #pragma unroll
                for (int rr = 0; rr < 4; ++rr)
                    acc[mt][nt][rr] = 0.0f;

        // ---- k-loop: 8 steps of k=8; A rounded to tf32 on the fly ----
        #pragma unroll
        for (int ks = 0; ks < 8; ++ks) {
            uint32_t a[4][4];
            #pragma unroll
            for (int mt = 0; mt < 4; ++mt) {
                const float* ap = A_s + (mgrp * 64 + mt * 16 + qrow) * A_STRIDE
                                      + ks * 8 + qcol;
                a[mt][0] = __float_as_uint(to_tf32(ap[0]));
                a[mt][1] = __float_as_uint(to_tf32(ap[8 * A_STRIDE]));
                a[mt][2] = __float_as_uint(to_tf32(ap[4]));
                a[mt][3] = __float_as_uint(to_tf32(ap[8 * A_STRIDE + 4]));
            }
            uint32_t b[4][2];
            #pragma unroll
            for (int nt = 0; nt < 4; ++nt) {
                const float* bp = B_s + (ks * 8 + qcol) * B_STRIDE
                                      + ngrp * 32 + nt * 8 + qrow;
                b[nt][0] = __float_as_uint(bp[0]);
                b[nt][1] = __float_as_uint(bp[4 * B_STRIDE]);
            }
            #pragma unroll
            for (int mt = 0; mt < 4; ++mt)
                #pragma unroll
                for (int nt = 0; nt < 4; ++nt)
                    MMA_TF32(acc[mt][nt], a[mt], b[nt]);
        }

        // ---- epilogue: relu(+b1)*w2, sum over this warp's 32 cols ----
        float part[4][2];
        #pragma unroll
        for (int mt = 0; mt < 4; ++mt) {
            #pragma unroll
            for (int hf = 0; hf < 2; ++hf) {
                float s = 0.0f;
                #pragma unroll
                for (int nt = 0; nt < 4; ++nt) {
                    int col = ngrp * 32 + nt * 8 + qcol * 2;
                    float2 p0 = bw[col];
                    float2 p1 = bw[col + 1];
                    float d0 = fmaxf(acc[mt][nt][hf * 2 + 0] + p0.x, 0.0f);
                    float d1 = fmaxf(acc[mt][nt][hf * 2 + 1] + p1.x, 0.0f);
                    s = fmaf(d0, p0.y, s);
                    s = fmaf(d1, p1.y, s);
                }
                part[mt][hf] = s;
            }
        }
        #pragma unroll
        for (int off = 1; off < 4; off <<= 1)
            #pragma unroll
            for (int mt = 0; mt < 4; ++mt)
                #pragma unroll
                for (int hf = 0; hf < 2; ++hf)
                    part[mt][hf] += __shfl_xor_sync(0xffffffffu, part[mt][hf], off);

        if (qcol == 0) {
            #pragma unroll
            for (int mt = 0; mt < 4; ++mt)
                #pragma unroll
                for (int hf = 0; hf < 2; ++hf) {
                    int row = mgrp * 64 + mt * 16 + hf * 8 + qrow;
                    ep[row * 5 + ngrp] = part[mt][hf];
                }
        }
        __syncthreads();     // ep ready; all k-loop A_s reads done

        if (t < ROWS_PER_TILE) {
            float s = ep[t * 5 + 0] + ep[t * 5 + 1]
                    + ep[t * 5 + 2] + ep[t * 5 + 3];
            float y  = fmaxf(s + b2v, 0.0f);
            int rowg = rowbase + t;
            float xv = X[(size_t)rowg * F_TOT + f];
            reinterpret_cast<float2*>(out)[(size_t)rowg * F_TOT + f] =
                make_float2(xv, y);
        }
        // next iteration's post-wait __syncthreads orders ep reads vs reuse
    }
}

// ---------------- launch ----------------
extern "C" void kernel_launch(void* const* d_in, const int* in_sizes, int n_in,
                              void* d_out, int out_size)
{
    const float* X  = (const float*)d_in[0];
    const float* r_ = (const float*)d_in[1];
    const float* W1 = (const float*)d_in[2];
    const float* b1 = (const float*)d_in[3];
    const float* W2 = (const float*)d_in[4];
    const float* b2 = (const float*)d_in[5];
    float* out = (float*)d_out;

    cudaFuncSetAttribute(cont_mlp_mma_kernel,
                         cudaFuncAttributeMaxDynamicSharedMemorySize, SMEM_BYTES);

    dim3 grid(B_TOT / ROWS_PER_BLK, F_TOT);   // (32, 32)
    cont_mlp_mma_kernel<<<grid, THREADS, SMEM_BYTES>>>(X, r_, W1, b1, W2, b2, out);
}